// round 14
// baseline (speedup 1.0000x reference)
#include <cuda_runtime.h>
#include <cuda_fp16.h>
#include <cstdint>

#define T_TREES 20
#define N_INT   31
#define F_DIM   128
#define TILE_M  384
#define THREADS 768            // 24 warps, 16 rows/warp

// ---------------- smem layout (bytes) ----------------
#define B_STRIDE 272                       // 128 fp16 = 256B + 16B pad (ldmatrix conflict-free)
#define B_TREE   (32 * B_STRIDE)           // 8704 per tree
#define SM_B     0
#define SM_G     (T_TREES * B_TREE)                  // 174080
#define PSTR     392                                 // words per pair-slot column (384 rows + 8)
#define HOFF     3536                                // side-1 word offset (>=8*PSTR+384, ==16 mod 32)
#define G_WORDS  (HOFF + 8 * PSTR)                   // 6672 words
#define SM_HB    (SM_G + G_WORDS * 4)                // 200768: half2 bias pairs (permuted), 16/tree
#define SM_COEF  (SM_HB + T_TREES * 16 * 4)          // 202048: uint2 {base_h2, delta_h2}, 16/tree
#define SMEM_TOTAL (SM_COEF + T_TREES * 16 * 8)      // 204608

// B-column permutation: side0 (even pair-cols) = left subtree, side1 = right.
// column c: j=c>>2, s=(c>>1)&1, h=c&1 -> node = SIDE[s][2j+h]
__device__ __constant__ int PERM[32] = {
    15,16, 23,24, 17,18, 25,26, 19,20, 27,28, 21,22, 29,30,
     7, 8, 11,12,  9,10, 13,14,  3, 4,  5, 6,  1, 0,  2,31 };

__device__ __forceinline__ uint32_t smem_u32(const void* p) {
    uint32_t a;
    asm("{ .reg .u64 t; cvta.to.shared.u64 t, %1; cvt.u32.u64 %0, t; }" : "=r"(a) : "l"(p));
    return a;
}

// packed sigmoid pair: g = 0.5*tanh(0.5*logit + hb) + 0.5   (hb = 0.5*bias)
__device__ __forceinline__ uint32_t sig2(uint32_t logit_h2, __half2 hb) {
    const __half2 H05 = __half2half2(__ushort_as_half(0x3800));
    __half2 z = __hfma2(*(__half2*)&logit_h2, H05, hb);
    uint32_t zi = *(uint32_t*)&z, to;
    asm("tanh.approx.f16x2 %0, %1;" : "=r"(to) : "r"(zi));
    __half2 g = __hfma2(*(__half2*)&to, H05, H05);
    return *(uint32_t*)&g;
}

#define LDSM_X4(d0, d1, d2, d3, addr) \
    asm volatile("ldmatrix.sync.aligned.m8n8.x4.shared.b16 {%0,%1,%2,%3}, [%4];" \
                 : "=r"(d0), "=r"(d1), "=r"(d2), "=r"(d3) : "r"(addr))

#define MMA_16816_F16(d, a, b0v, b1v) \
    asm volatile("mma.sync.aligned.m16n8k16.row.col.f16.f16.f16.f16 " \
                 "{%0,%1}, {%2,%3,%4,%5}, {%6,%7}, {%0,%1};" \
                 : "+r"((d)[0]), "+r"((d)[1]) \
                 : "r"((a)[0]), "r"((a)[1]), "r"((a)[2]), "r"((a)[3]), \
                   "r"(b0v), "r"(b1v))

// One tree's K=128 GEMM for this warp's 16 rows (reuses c registers).
__device__ __forceinline__ void mma_tree(uint32_t c[4][2], uint32_t bbase,
                                         const uint32_t A[8][4]) {
#pragma unroll
    for (int i = 0; i < 8; ++i) ((uint32_t*)c)[i] = 0u;
#pragma unroll
    for (int k = 0; k < 8; ++k) {
        uint32_t b0, b1, b2, b3, b4, b5, b6, b7;
        LDSM_X4(b0, b1, b2, b3, bbase + k * 32);          // cols 0..15
        LDSM_X4(b4, b5, b6, b7, bbase + k * 32 + 4352);   // cols 16..31
        MMA_16816_F16(c[0], A[k], b0, b1);
        MMA_16816_F16(c[1], A[k], b2, b3);
        MMA_16816_F16(c[2], A[k], b4, b5);
        MMA_16816_F16(c[3], A[k], b6, b7);
    }
}

// ---------------------------------------------------------------------------
// Persistent kernel, 24 warps/CTA, 16 rows/warp. Combine split across lane
// pairs (even=left subtree, odd=right), merged by one shfl at the root.
// ---------------------------------------------------------------------------
__global__ __launch_bounds__(THREADS)
void forest_hmma(const float* __restrict__ x,  const float* __restrict__ sw,
                 const float* __restrict__ sb, const float* __restrict__ ll,
                 const float* __restrict__ tw, const float* __restrict__ fm,
                 float* __restrict__ out, int n_tiles, int Btot)
{
    extern __shared__ unsigned char smem[];
    const int tid  = threadIdx.x;
    const int lane = tid & 31;
    const int warp = tid >> 5;

    // ---------- CTA init ----------
    // B tiles, columns permuted by PERM (column c holds node PERM[c]'s weights)
    for (int idx = tid; idx < T_TREES * 32 * F_DIM; idx += THREADS) {
        int t = idx >> 12, ccol = (idx >> 7) & 31, k = idx & 127;
        int n = PERM[ccol];
        float v = (n < N_INT) ? sw[(t * N_INT + n) * F_DIM + k] * fm[t * F_DIM + k] : 0.f;
        *(__half*)(smem + SM_B + t * B_TREE + ccol * B_STRIDE + k * 2) = __float2half_rn(v);
    }
    __half2* hb = (__half2*)(smem + SM_HB);
    for (int idx = tid; idx < T_TREES * 16; idx += THREADS) {
        int t = idx >> 4, pr = idx & 15;
        int n0 = PERM[2 * pr], n1 = PERM[2 * pr + 1];
        float b0 = (n0 < N_INT) ? 0.5f * sb[t * N_INT + n0] : 0.f;
        float b1 = (n1 < N_INT) ? 0.5f * sb[t * N_INT + n1] : 0.f;
        hb[idx] = __floats2half2_rn(b0, b1);
    }
    if (tid < T_TREES) {
        int t = tid;
        float mx = tw[0];
        for (int i = 1; i < T_TREES; ++i) mx = fmaxf(mx, tw[i]);
        float s = 0.f;
        for (int i = 0; i < T_TREES; ++i) s += expf(tw[i] - mx);
        float w = expf(tw[t] - mx) / s;
        uint2* cf = (uint2*)(smem + SM_COEF) + t * 16;
        for (int p = 0; p < 16; ++p) {
            float a0 = ll[(t * 32 + 2 * p) * 2 + 0], b0 = ll[(t * 32 + 2 * p) * 2 + 1];
            float m0 = fmaxf(a0, b0), e0 = expf(a0 - m0), f0 = expf(b0 - m0);
            float i0 = w / (e0 + f0);
            float a1 = ll[(t * 32 + 2 * p + 1) * 2 + 0], b1 = ll[(t * 32 + 2 * p + 1) * 2 + 1];
            float m1 = fmaxf(a1, b1), e1 = expf(a1 - m1), f1 = expf(b1 - m1);
            float i1 = w / (e1 + f1);
            float c0l = e0 * i0, c1l = f0 * i0;
            __half2 base  = __floats2half2_rn(c0l, c1l);
            __half2 delta = __floats2half2_rn(e1 * i1 - c0l, f1 * i1 - c1l);
            uint2 v; v.x = *(uint32_t*)&base; v.y = *(uint32_t*)&delta;
            cf[p] = v;
        }
    }
    __syncthreads();

    const uint32_t sBu = smem_u32(smem) + SM_B;
    const int r8 = lane & 7, gq = lane >> 3;
    const uint32_t lm_off = (uint32_t)(((gq >> 1) * 8 + r8) * B_STRIDE + (gq & 1) * 16);

    const int r0 = lane >> 2;          // frag row within 8
    const int c0 = (lane & 3) * 2;     // frag col pair
    const int q  = lane & 3;
    uint32_t* sGp = (uint32_t*)(smem + SM_G);

    // combine-side identity: even lane = left subtree, odd = right
    const int side = lane & 1;
    const int Rrow = warp * 16 + (lane >> 1);          // row this lane combines
    const uint32_t gread = (uint32_t)(side * HOFF) + Rrow;

    // writer slot for pair-col pr = 4nb+q: s=pr&1=q&1, j=pr>>1=2nb+(q>>1)
    const uint32_t wbase0 = (uint32_t)((q & 1) * HOFF + (q >> 1) * PSTR) + warp * 16 + r0;

    // ---------- tile loop ----------
    for (int tile = blockIdx.x; tile < n_tiles; tile += gridDim.x) {
        const long rb = (long)tile * TILE_M + warp * 16;

        // A fragments: 16 rows x K=128 -> 32 fp16x2 regs (rows clamped on tail tile)
        uint32_t A[8][4];
#pragma unroll
        for (int k = 0; k < 8; ++k)
#pragma unroll
            for (int j = 0; j < 4; ++j) {
                long row = rb + r0 + 8 * (j & 1);
                if (row >= Btot) row = Btot - 1;
                int col = k * 16 + c0 + 8 * (j >> 1);
                float2 v = *(const float2*)(x + row * F_DIM + col);
                __half2 p = __floats2half2_rn(v.x, v.y);
                A[k][j] = *(uint32_t*)&p;
            }

        float acc0 = 0.f, acc1 = 0.f;
        uint32_t c[4][2];
        mma_tree(c, sBu + lm_off, A);                  // prologue: tree 0

        for (int t = 0; t < T_TREES; ++t) {
            // sigmoid + conflict-free STS.32 into (side, slot) gate layout
            const __half2* hbt = (const __half2*)(smem + SM_HB) + t * 16;
#pragma unroll
            for (int nb = 0; nb < 4; ++nb) {
                __half2 hbv = hbt[4 * nb + q];
                uint32_t* col = sGp + wbase0 + (uint32_t)(2 * nb) * PSTR;
                col[0] = sig2(c[nb][0], hbv);
                col[8] = sig2(c[nb][1], hbv);
            }
            __syncwarp();   // warp wrote exactly its own 16 rows — warp-private

            // accumulators dead: start tree t+1's GEMM (hides LDSM/MMA latency)
            if (t + 1 < T_TREES)
                mma_tree(c, sBu + (t + 1) * B_TREE + lm_off, A);

            // 8 conflict-free LDS.32: this side's gate words for row Rrow
            uint32_t gw[8];
#pragma unroll
            for (int j = 0; j < 8; ++j) gw[j] = sGp[gread + j * PSTR];

            // half-tree combine (15 gates), coefs cf[8*side + i]
            const uint2* cf = (const uint2*)(smem + SM_COEF) + t * 16 + 8 * side;
            __half2 p[8];
#pragma unroll
            for (int i = 0; i < 8; ++i) {              // level 4 (8 sub-leaf pairs)
                uint2 cv = cf[i];
                __half2 g = (i & 1) ? __high2half2(*(__half2*)&gw[i >> 1])
                                    : __low2half2(*(__half2*)&gw[i >> 1]);
                p[i] = __hfma2(g, *(__half2*)&cv.y, *(__half2*)&cv.x);
            }
#pragma unroll
            for (int i = 0; i < 4; ++i) {              // level 3 (words 4,5)
                __half2 g = (i & 1) ? __high2half2(*(__half2*)&gw[4 + (i >> 1)])
                                    : __low2half2(*(__half2*)&gw[4 + (i >> 1)]);
                p[i] = __hfma2(g, __hsub2(p[2 * i + 1], p[2 * i]), p[2 * i]);
            }
#pragma unroll
            for (int i = 0; i < 2; ++i) {              // level 2 (word 6)
                __half2 g = (i & 1) ? __high2half2(*(__half2*)&gw[6])
                                    : __low2half2(*(__half2*)&gw[6]);
                p[i] = __hfma2(g, __hsub2(p[2 * i + 1], p[2 * i]), p[2 * i]);
            }
            // level 1 (word 7 lo = node1/node2)
            __half2 g1 = __low2half2(*(__half2*)&gw[7]);
            __half2 pS = __hfma2(g1, __hsub2(p[1], p[0]), p[0]);

            // merge at root: even lane has left value + root gate (word 7 hi)
            uint32_t pSu = *(uint32_t*)&pS;
            uint32_t pOu = __shfl_xor_sync(0xFFFFFFFFu, pSu, 1);
            if (side == 0) {
                __half2 pR = *(__half2*)&pOu;
                __half2 g0 = __high2half2(*(__half2*)&gw[7]);
                __half2 r  = __hfma2(g0, __hsub2(pR, pS), pS);
                float2 rf  = __half22float2(r);
                acc0 += rf.x;
                acc1 += rf.y;
            }
            __syncwarp();   // gates consumed before next tree's store overwrites
        }

        if (side == 0) {
            long row = (long)tile * TILE_M + Rrow;
            if (row < Btot)
                ((float2*)out)[row] = make_float2(acc0, acc1);
        }
    }
}

// ---------------------------------------------------------------------------
// metadata order: x, split_weights, split_bias, leaf_logits, tree_weights,
//                 feature_masks.  output: [B,2] float32
// ---------------------------------------------------------------------------
extern "C" void kernel_launch(void* const* d_in, const int* in_sizes, int n_in,
                              void* d_out, int out_size) {
    const float* x  = (const float*)d_in[0];
    const float* sw = (const float*)d_in[1];
    const float* sb = (const float*)d_in[2];
    const float* ll = (const float*)d_in[3];
    const float* tw = (const float*)d_in[4];
    const float* fm = (const float*)d_in[5];
    float* out = (float*)d_out;

    const int Btot = in_sizes[0] / F_DIM;             // 131072
    const int n_tiles = (Btot + TILE_M - 1) / TILE_M; // 342

    int nsm = 148;
    cudaDeviceGetAttribute(&nsm, cudaDevAttrMultiProcessorCount, 0);

    cudaFuncSetAttribute(forest_hmma, cudaFuncAttributeMaxDynamicSharedMemorySize, SMEM_TOTAL);
    forest_hmma<<<nsm, THREADS, SMEM_TOTAL>>>(x, sw, sb, ll, tw, fm, out, n_tiles, Btot);
}